// round 5
// baseline (speedup 1.0000x reference)
#include <cuda_runtime.h>
#include <cuda_bf16.h>
#include <math.h>
#include <stdint.h>

// Problem constants
#define NB   96   // nodes
#define DD   64   // feature dim
#define BS   16   // batch
#define TT   13   // sequence length (12 steps)
#define SZ   (BS * NB * DD)

#define STU  36   // shared row stride in u32 (= 72 bf16): conflict-free ldmatrix

// Scratch state (allocation-free rule: __device__ globals)
__device__ float g_hidden[SZ];
__device__ float g_S[2][SZ];     // double-buffered: cross-block read hazard within a step
__device__ float g_R[SZ];        // own-row only: no double buffer needed
__device__ float g_Xall[NB * 3 * DD];   // per-skill input projections (xr|xi|xn), bias included

// W2^T split into bf16 hi/lo, packed 2 k's per u32: layout [d][kp]
__device__ uint32_t g_w2t_hi[2048];
__device__ uint32_t g_w2t_lo[2048];

__device__ __forceinline__ float tanh_fast(float x) {
    float y;
    asm("tanh.approx.f32 %0, %1;" : "=f"(y) : "f"(x));
    return y;
}
__device__ __forceinline__ float sigmoid_acc(float x) {
    return 1.0f / (1.0f + expf(-x));
}
__device__ __forceinline__ uint32_t smem_u32(const void* p) {
    uint32_t a;
    asm("{ .reg .u64 t; cvta.to.shared.u64 t, %1; cvt.u32.u64 %0, t; }" : "=r"(a) : "l"(p));
    return a;
}
__device__ __forceinline__ void ldm_x4(uint32_t a[4], uint32_t addr) {
    asm volatile("ldmatrix.sync.aligned.m8n8.x4.shared.b16 {%0,%1,%2,%3}, [%4];"
        : "=r"(a[0]), "=r"(a[1]), "=r"(a[2]), "=r"(a[3]) : "r"(addr));
}
__device__ __forceinline__ void ldm_x2(uint32_t& r0, uint32_t& r1, uint32_t addr) {
    asm volatile("ldmatrix.sync.aligned.m8n8.x2.shared.b16 {%0,%1}, [%2];"
        : "=r"(r0), "=r"(r1) : "r"(addr));
}
__device__ __forceinline__ void mma_bf16(float c[4], const uint32_t a[4],
                                         uint32_t b0, uint32_t b1) {
    asm volatile("mma.sync.aligned.m16n8k16.row.col.f32.bf16.bf16.f32 "
        "{%0,%1,%2,%3}, {%4,%5,%6,%7}, {%8,%9}, {%0,%1,%2,%3};"
        : "+f"(c[0]), "+f"(c[1]), "+f"(c[2]), "+f"(c[3])
        : "r"(a[0]), "r"(a[1]), "r"(a[2]), "r"(a[3]), "r"(b0), "r"(b1));
}
__device__ __forceinline__ uint32_t pack_bf16x2(float lo_val, float hi_val) {
    __nv_bfloat16 l = __float2bfloat16(lo_val);
    __nv_bfloat16 h = __float2bfloat16(hi_val);
    return ((uint32_t)__bfloat16_as_ushort(h) << 16) | __bfloat16_as_ushort(l);
}

// ---------------------------------------------------------------------------
__global__ void kInit() {
    int idx = blockIdx.x * blockDim.x + threadIdx.x;
    if (idx < SZ) {
        g_hidden[idx] = 0.0f;
        g_S[0][idx] = 0.0f;
        g_S[1][idx] = 0.0f;
        g_R[idx] = 0.0f;
    }
}

// Prep (once): Wt[d][k] = W2[k][d], bf16 hi/lo split, 2 k's packed per u32.
__global__ void kPrep(const float* __restrict__ W2) {
    int tid = threadIdx.x;
    for (int idx = tid; idx < 2048; idx += 256) {
        int d  = idx >> 5;
        int kp = idx & 31;
        float w0 = W2[(2 * kp)     * DD + d];
        float w1 = W2[(2 * kp + 1) * DD + d];
        __nv_bfloat16 h0 = __float2bfloat16(w0);
        __nv_bfloat16 h1 = __float2bfloat16(w1);
        g_w2t_hi[idx] = ((uint32_t)__bfloat16_as_ushort(h1) << 16) | __bfloat16_as_ushort(h0);
        g_w2t_lo[idx] = pack_bf16x2(w0 - __bfloat162float(h0), w1 - __bfloat162float(h1));
    }
}

// Prep (once): per-skill input projections Xall[s][g*64+d] = b_g[d] + emb[s]@W_g
__global__ void kPrepX(const float* __restrict__ emb,
                       const float* __restrict__ W_ir, const float* __restrict__ b_ir,
                       const float* __restrict__ W_ii, const float* __restrict__ b_ii,
                       const float* __restrict__ W_in, const float* __restrict__ b_in) {
    __shared__ float sE[DD];
    int s = blockIdx.x;
    int tid = threadIdx.x;          // 192 threads
    if (tid < DD) sE[tid] = emb[s * DD + tid];
    __syncthreads();
    int g = tid >> 6, d = tid & 63;
    const float* W  = (g == 0) ? W_ir : (g == 1) ? W_ii : W_in;
    const float* bb = (g == 0) ? b_ir : (g == 1) ? b_ii : b_in;
    float a = bb[d];
#pragma unroll 8
    for (int k = 0; k < DD; k++) a = fmaf(sE[k], W[k * DD + d], a);
    g_Xall[s * (3 * DD) + g * DD + d] = a;
}

// ---------------------------------------------------------------------------
// Fused step kernel: per (b,i) CTA
//  Phase 1 (HMMA): T = tanh(Sprev[b,j]+R[b,i]+bm1); C = T@W2 (3-pass bf16 split);
//                  agg = (1/96) sum_j adj[b,i,j] * tanh(C+b2)
//  Phase 2 (GEMVs): GRU gates -> hidden update -> pred head (3 layers) -> out;
//                  Snext/R rows from new hidden.
// ---------------------------------------------------------------------------
__global__ void __launch_bounds__(256) kStep(
    int t,
    const int*   __restrict__ skill_seq,
    const float* __restrict__ adj,
    const float* __restrict__ bm1,   const float* __restrict__ b2,
    const float* __restrict__ W_hr,  const float* __restrict__ W_hi,
    const float* __restrict__ W_hh,
    const float* __restrict__ W_o1,  const float* __restrict__ b_o1,
    const float* __restrict__ W_o2,  const float* __restrict__ b_o2,
    const float* __restrict__ W_o3,  const float* __restrict__ b_o3,
    const float* __restrict__ W_msg1,
    float* __restrict__ out)
{
    __shared__ uint32_t sThi[NB * STU];   // 13824 B   (phase-2 scratch aliases here)
    __shared__ uint32_t sTlo[NB * STU];   // 13824 B
    __shared__ uint32_t sWhi[DD * STU];   //  9216 B
    __shared__ uint32_t sWlo[DD * STU];   //  9216 B
    __shared__ float sAdj[NB];
    __shared__ float sB2[DD];
    __shared__ float sRv[DD];
    __shared__ float sRed[2][DD];

    const int bx   = blockIdx.x;
    const int b    = bx / NB;
    const int i    = bx % NB;
    const int tid  = threadIdx.x;
    const int wid  = tid >> 5;
    const int lane = tid & 31;
    const int row  = (b * NB + i) * DD;

    const float* Sprev = g_S[t & 1];
    float*       Snext = g_S[(t + 1) & 1];

    // stage W images + adj row + biases
    for (int idx = tid; idx < 2048; idx += 256) {
        int d = idx >> 5, kp = idx & 31;
        sWhi[d * STU + kp] = g_w2t_hi[idx];
        sWlo[d * STU + kp] = g_w2t_lo[idx];
    }
    if (tid < DD) {
        sRv[tid] = g_R[row + tid] + bm1[tid];
        sB2[tid] = b2[tid];
    }
    if (tid < NB) sAdj[tid] = adj[(b * NB + i) * NB + tid];
    __syncthreads();

    // build T = tanh(Sprev[b,j,:] + rv) -> bf16 hi/lo (2 k's per u32)
    const float* Sb = &Sprev[b * NB * DD];
#pragma unroll
    for (int p = 0; p < 12; p++) {
        int idx = tid + p * 256;          // 0..3071
        int j  = idx >> 5;
        int kp = idx & 31;
        float2 s = *reinterpret_cast<const float2*>(&Sb[j * DD + kp * 2]);
        float t0 = tanh_fast(s.x + sRv[kp * 2]);
        float t1 = tanh_fast(s.y + sRv[kp * 2 + 1]);
        __nv_bfloat16 h0 = __float2bfloat16(t0);
        __nv_bfloat16 h1 = __float2bfloat16(t1);
        sThi[j * STU + kp] = ((uint32_t)__bfloat16_as_ushort(h1) << 16) | __bfloat16_as_ushort(h0);
        sTlo[j * STU + kp] = pack_bf16x2(t0 - __bfloat162float(h0), t1 - __bfloat162float(h1));
    }
    __syncthreads();

    // ---- HMMA main: warp (wm, wn); warp owns 3 m-tiles x 2 n-tiles ----
    const int wn = wid & 3;
    const int wm = wid >> 2;
    const int d0 = wn * 16;

    const uint32_t tThi = smem_u32(sThi);
    const uint32_t tTlo = smem_u32(sTlo);
    const uint32_t tWhi = smem_u32(sWhi);
    const uint32_t tWlo = smem_u32(sWlo);

    const int a_joff = (lane & 7) + ((lane & 8) ? 8 : 0);
    const int a_koff = (lane & 16) ? 8 : 0;
    const int bl     = lane & 15;
    const int b_nrow = bl & 7;
    const int b_koff = (bl & 8) ? 8 : 0;

    float c[3][2][4];
#pragma unroll
    for (int mt = 0; mt < 3; mt++)
#pragma unroll
        for (int nt = 0; nt < 2; nt++)
#pragma unroll
            for (int r = 0; r < 4; r++) c[mt][nt][r] = 0.0f;

#pragma unroll
    for (int pass = 0; pass < 3; pass++) {
        const uint32_t Ab = (pass == 1) ? tTlo : tThi;
        const uint32_t Bb = (pass == 2) ? tWlo : tWhi;
#pragma unroll
        for (int ks = 0; ks < 4; ks++) {
            const int k0 = ks * 16;
            uint32_t bf[2][2];
#pragma unroll
            for (int nt = 0; nt < 2; nt++) {
                uint32_t baddr = Bb + ((d0 + nt * 8 + b_nrow) * STU + ((k0 + b_koff) >> 1)) * 4;
                ldm_x2(bf[nt][0], bf[nt][1], baddr);
            }
#pragma unroll
            for (int mt = 0; mt < 3; mt++) {
                const int jm = (wm * 3 + mt) * 16;
                uint32_t af[4];
                uint32_t aaddr = Ab + ((jm + a_joff) * STU + ((k0 + a_koff) >> 1)) * 4;
                ldm_x4(af, aaddr);
                mma_bf16(c[mt][0], af, bf[0][0], bf[0][1]);
                mma_bf16(c[mt][1], af, bf[1][0], bf[1][1]);
            }
        }
    }

    // ---- epilogue: tanh + adj-weighted j-reduction in fragments ----
    const int g4 = lane >> 2;
    const int c4 = lane & 3;
    float acc[2][2] = {{0.f, 0.f}, {0.f, 0.f}};
    float b2v[2][2];
#pragma unroll
    for (int nt = 0; nt < 2; nt++) {
        b2v[nt][0] = sB2[d0 + nt * 8 + 2 * c4];
        b2v[nt][1] = sB2[d0 + nt * 8 + 2 * c4 + 1];
    }
#pragma unroll
    for (int mt = 0; mt < 3; mt++) {
        const int jb = (wm * 3 + mt) * 16;
        float aj0 = sAdj[jb + g4];
        float aj1 = sAdj[jb + 8 + g4];
#pragma unroll
        for (int nt = 0; nt < 2; nt++) {
            acc[nt][0] = fmaf(aj0, tanh_fast(c[mt][nt][0] + b2v[nt][0]), acc[nt][0]);
            acc[nt][1] = fmaf(aj0, tanh_fast(c[mt][nt][1] + b2v[nt][1]), acc[nt][1]);
            acc[nt][0] = fmaf(aj1, tanh_fast(c[mt][nt][2] + b2v[nt][0]), acc[nt][0]);
            acc[nt][1] = fmaf(aj1, tanh_fast(c[mt][nt][3] + b2v[nt][1]), acc[nt][1]);
        }
    }
#pragma unroll
    for (int off = 4; off <= 16; off <<= 1) {
#pragma unroll
        for (int nt = 0; nt < 2; nt++) {
#pragma unroll
            for (int cc = 0; cc < 2; cc++)
                acc[nt][cc] += __shfl_xor_sync(0xffffffffu, acc[nt][cc], off);
        }
    }
    if (lane < 4) {
        sRed[wm][d0 + 2 * lane]         = acc[0][0];
        sRed[wm][d0 + 2 * lane + 1]     = acc[0][1];
        sRed[wm][d0 + 8 + 2 * lane]     = acc[1][0];
        sRed[wm][d0 + 8 + 2 * lane + 1] = acc[1][1];
    }
    __syncthreads();

    // ---- phase 2: alias scratch onto dead sThi region ----
    float* sAgg  = reinterpret_cast<float*>(sThi);        // [64]
    float* sGate = sAgg + DD;                             // [3*64]
    float* sHN   = sGate + 3 * DD;                        // [64]
    float* sP    = sHN + DD;                              // [64]
    float* sP2   = sP + DD;                               // [64]

    if (tid < DD)
        sAgg[tid] = (sRed[0][tid] + sRed[1][tid]) * (1.0f / 96.0f);
    __syncthreads();

    // Stage A: GRU gate pre-activations  (warps 0..5: 3 GEMVs x 2 warps)
    if (wid < 6) {
        const int g = wid >> 1;
        const int d = (wid & 1) * 32 + lane;
        const float* W = (g == 0) ? W_hr : (g == 1) ? W_hi : W_hh;
        float a = 0.0f;
#pragma unroll 8
        for (int k = 0; k < DD; k++) a = fmaf(sAgg[k], W[k * DD + d], a);
        sGate[g * DD + d] = a;
    }
    __syncthreads();

    // GRU update (64 threads)
    if (tid < DD) {
        const int d = tid;
        int skill = skill_seq[b * TT + t];
        const float* X = &g_Xall[skill * (3 * DD)];
        float rr = sigmoid_acc(X[d] + sGate[d]);
        float ii = sigmoid_acc(X[DD + d] + sGate[DD + d]);
        float nn = tanhf(X[2 * DD + d] + rr * sGate[2 * DD + d]);
        float h  = g_hidden[row + d];
        float hn = (1.0f - ii) * nn + ii * h;
        g_hidden[row + d] = hn;
        sHN[d] = hn;
    }
    __syncthreads();

    // Stage B: pred layer1 + Snext + R  (warps 0..5)
    if (wid < 6) {
        const int g = wid >> 1;
        const int d = (wid & 1) * 32 + lane;
        const float* W = (g == 0) ? W_o1 : (g == 1) ? W_msg1 : (W_msg1 + DD * DD);
        float a = 0.0f;
#pragma unroll 8
        for (int k = 0; k < DD; k++) a = fmaf(sHN[k], W[k * DD + d], a);
        if (g == 0)      sP[d] = fmaxf(a + b_o1[d], 0.0f);
        else if (g == 1) Snext[row + d] = a;
        else             g_R[row + d] = a;
    }
    __syncthreads();

    // Stage C: pred layer2 (warps 0..1)
    if (wid < 2) {
        const int d = wid * 32 + lane;
        float a = 0.0f;
#pragma unroll 8
        for (int k = 0; k < DD; k++) a = fmaf(sP[k], W_o2[k * DD + d], a);
        sP2[d] = fmaxf(a + b_o2[d], 0.0f);
    }
    __syncthreads();

    // Stage D: pred layer3 -> out (warps 0..1)
    if (wid < 2) {
        const int d = wid * 32 + lane;
        float a = 0.0f;
#pragma unroll 8
        for (int k = 0; k < DD; k++) a = fmaf(sP2[k], W_o3[k * DD + d], a);
        out[(((size_t)b * 12 + t) * NB + i) * DD + d] = a + b_o3[d];
    }
}

// ---------------------------------------------------------------------------
extern "C" void kernel_launch(void* const* d_in, const int* in_sizes, int n_in,
                              void* d_out, int out_size) {
    const int*   skill_seq = (const int*)  d_in[0];
    const float* adj       = (const float*)d_in[1];
    const float* node_emb  = (const float*)d_in[2];
    const float* W_msg1    = (const float*)d_in[3];
    const float* b_msg1    = (const float*)d_in[4];
    const float* W_msg2    = (const float*)d_in[5];
    const float* b_msg2    = (const float*)d_in[6];
    const float* W_hr      = (const float*)d_in[7];
    const float* W_hi      = (const float*)d_in[8];
    const float* W_hh      = (const float*)d_in[9];
    const float* W_ir      = (const float*)d_in[10];
    const float* b_ir      = (const float*)d_in[11];
    const float* W_ii      = (const float*)d_in[12];
    const float* b_ii      = (const float*)d_in[13];
    const float* W_in      = (const float*)d_in[14];
    const float* b_in      = (const float*)d_in[15];
    const float* W_o1      = (const float*)d_in[16];
    const float* b_o1      = (const float*)d_in[17];
    const float* W_o2      = (const float*)d_in[18];
    const float* b_o2      = (const float*)d_in[19];
    const float* W_o3      = (const float*)d_in[20];
    const float* b_o3      = (const float*)d_in[21];
    float* out = (float*)d_out;

    kInit<<<(SZ + 255) / 256, 256>>>();
    kPrep<<<1, 256>>>(W_msg2);
    kPrepX<<<NB, 192>>>(node_emb, W_ir, b_ir, W_ii, b_ii, W_in, b_in);

    for (int t = 0; t < TT - 1; t++) {
        kStep<<<BS * NB, 256>>>(t, skill_seq, adj,
                                b_msg1, b_msg2,
                                W_hr, W_hi, W_hh,
                                W_o1, b_o1, W_o2, b_o2, W_o3, b_o3,
                                W_msg1, out);
    }
}

// round 6
// speedup vs baseline: 1.0083x; 1.0083x over previous
#include <cuda_runtime.h>
#include <cuda_bf16.h>
#include <math.h>
#include <stdint.h>

// Problem constants
#define NB   96   // nodes
#define DD   64   // feature dim
#define BS   16   // batch
#define TT   13   // sequence length (12 steps)
#define SZ   (BS * NB * DD)

#define STU  36   // shared row stride in u32 (= 72 bf16): conflict-free ldmatrix

// Scratch state (allocation-free rule: __device__ globals)
__device__ float g_hidden[SZ];
__device__ float g_S[2][SZ];     // double-buffered: cross-block read hazard within a step
__device__ float g_R[SZ];        // own-row only: no double buffer needed
__device__ float g_Xall[NB * 3 * DD];   // per-skill input projections (xr|xi|xn), bias included

// W2^T split into bf16 hi/lo, packed 2 k's per u32: layout [d][kp]
__device__ uint32_t g_w2t_hi[2048];
__device__ uint32_t g_w2t_lo[2048];

__device__ __forceinline__ float tanh_fast(float x) {
    float y;
    asm("tanh.approx.f32 %0, %1;" : "=f"(y) : "f"(x));
    return y;
}
__device__ __forceinline__ float sigmoid_acc(float x) {
    return 1.0f / (1.0f + expf(-x));
}
__device__ __forceinline__ uint32_t smem_u32(const void* p) {
    uint32_t a;
    asm("{ .reg .u64 t; cvta.to.shared.u64 t, %1; cvt.u32.u64 %0, t; }" : "=r"(a) : "l"(p));
    return a;
}
__device__ __forceinline__ void ldm_x4(uint32_t a[4], uint32_t addr) {
    asm volatile("ldmatrix.sync.aligned.m8n8.x4.shared.b16 {%0,%1,%2,%3}, [%4];"
        : "=r"(a[0]), "=r"(a[1]), "=r"(a[2]), "=r"(a[3]) : "r"(addr));
}
__device__ __forceinline__ void ldm_x2(uint32_t& r0, uint32_t& r1, uint32_t addr) {
    asm volatile("ldmatrix.sync.aligned.m8n8.x2.shared.b16 {%0,%1}, [%2];"
        : "=r"(r0), "=r"(r1) : "r"(addr));
}
__device__ __forceinline__ void mma_bf16(float c[4], const uint32_t a[4],
                                         uint32_t b0, uint32_t b1) {
    asm volatile("mma.sync.aligned.m16n8k16.row.col.f32.bf16.bf16.f32 "
        "{%0,%1,%2,%3}, {%4,%5,%6,%7}, {%8,%9}, {%0,%1,%2,%3};"
        : "+f"(c[0]), "+f"(c[1]), "+f"(c[2]), "+f"(c[3])
        : "r"(a[0]), "r"(a[1]), "r"(a[2]), "r"(a[3]), "r"(b0), "r"(b1));
}
__device__ __forceinline__ uint32_t pack_bf16x2(float lo_val, float hi_val) {
    __nv_bfloat16 l = __float2bfloat16(lo_val);
    __nv_bfloat16 h = __float2bfloat16(hi_val);
    return ((uint32_t)__bfloat16_as_ushort(h) << 16) | __bfloat16_as_ushort(l);
}

// ---------------------------------------------------------------------------
__global__ void kInit() {
    int idx = blockIdx.x * blockDim.x + threadIdx.x;
    if (idx < SZ) {
        g_hidden[idx] = 0.0f;
        g_S[0][idx] = 0.0f;
        g_S[1][idx] = 0.0f;
        g_R[idx] = 0.0f;
    }
}

// Prep (once): Wt[d][k] = W2[k][d], bf16 hi/lo split, 2 k's packed per u32.
__global__ void kPrep(const float* __restrict__ W2) {
    int tid = threadIdx.x;
    for (int idx = tid; idx < 2048; idx += 256) {
        int d  = idx >> 5;
        int kp = idx & 31;
        float w0 = W2[(2 * kp)     * DD + d];
        float w1 = W2[(2 * kp + 1) * DD + d];
        __nv_bfloat16 h0 = __float2bfloat16(w0);
        __nv_bfloat16 h1 = __float2bfloat16(w1);
        g_w2t_hi[idx] = ((uint32_t)__bfloat16_as_ushort(h1) << 16) | __bfloat16_as_ushort(h0);
        g_w2t_lo[idx] = pack_bf16x2(w0 - __bfloat162float(h0), w1 - __bfloat162float(h1));
    }
}

// Prep (once): per-skill input projections Xall[s][g*64+d] = b_g[d] + emb[s]@W_g
__global__ void kPrepX(const float* __restrict__ emb,
                       const float* __restrict__ W_ir, const float* __restrict__ b_ir,
                       const float* __restrict__ W_ii, const float* __restrict__ b_ii,
                       const float* __restrict__ W_in, const float* __restrict__ b_in) {
    __shared__ float sE[DD];
    int s = blockIdx.x;
    int tid = threadIdx.x;          // 192 threads
    if (tid < DD) sE[tid] = emb[s * DD + tid];
    __syncthreads();
    int g = tid >> 6, d = tid & 63;
    const float* W  = (g == 0) ? W_ir : (g == 1) ? W_ii : W_in;
    const float* bb = (g == 0) ? b_ir : (g == 1) ? b_ii : b_in;
    float a = bb[d];
#pragma unroll 8
    for (int k = 0; k < DD; k++) a = fmaf(sE[k], W[k * DD + d], a);
    g_Xall[s * (3 * DD) + g * DD + d] = a;
}

// ---------------------------------------------------------------------------
// Fused step kernel: per (b,i) CTA
//  Phase 1 (HMMA): T = tanh(Sprev[b,j]+R[b,i]+bm1); C = T@W2 (3-pass bf16 split);
//                  agg = (1/96) sum_j adj[b,i,j] * tanh(C+b2)
//  Phase 2 (GEMVs): GRU gates -> hidden update -> pred head (3 layers) -> out;
//                  Snext/R rows from new hidden.
// ---------------------------------------------------------------------------
__global__ void __launch_bounds__(256) kStep(
    int t,
    const int*   __restrict__ skill_seq,
    const float* __restrict__ adj,
    const float* __restrict__ bm1,   const float* __restrict__ b2,
    const float* __restrict__ W_hr,  const float* __restrict__ W_hi,
    const float* __restrict__ W_hh,
    const float* __restrict__ W_o1,  const float* __restrict__ b_o1,
    const float* __restrict__ W_o2,  const float* __restrict__ b_o2,
    const float* __restrict__ W_o3,  const float* __restrict__ b_o3,
    const float* __restrict__ W_msg1,
    float* __restrict__ out)
{
    __shared__ uint32_t sThi[NB * STU];   // 13824 B   (phase-2 scratch aliases here)
    __shared__ uint32_t sTlo[NB * STU];   // 13824 B
    __shared__ uint32_t sWhi[DD * STU];   //  9216 B
    __shared__ uint32_t sWlo[DD * STU];   //  9216 B
    __shared__ float sAdj[NB];
    __shared__ float sB2[DD];
    __shared__ float sRv[DD];
    __shared__ float sRed[2][DD];

    const int bx   = blockIdx.x;
    const int b    = bx / NB;
    const int i    = bx % NB;
    const int tid  = threadIdx.x;
    const int wid  = tid >> 5;
    const int lane = tid & 31;
    const int row  = (b * NB + i) * DD;

    const float* Sprev = g_S[t & 1];
    float*       Snext = g_S[(t + 1) & 1];

    // stage W images + adj row + biases
    for (int idx = tid; idx < 2048; idx += 256) {
        int d = idx >> 5, kp = idx & 31;
        sWhi[d * STU + kp] = g_w2t_hi[idx];
        sWlo[d * STU + kp] = g_w2t_lo[idx];
    }
    if (tid < DD) {
        sRv[tid] = g_R[row + tid] + bm1[tid];
        sB2[tid] = b2[tid];
    }
    if (tid < NB) sAdj[tid] = adj[(b * NB + i) * NB + tid];
    __syncthreads();

    // build T = tanh(Sprev[b,j,:] + rv) -> bf16 hi/lo (2 k's per u32)
    const float* Sb = &Sprev[b * NB * DD];
#pragma unroll
    for (int p = 0; p < 12; p++) {
        int idx = tid + p * 256;          // 0..3071
        int j  = idx >> 5;
        int kp = idx & 31;
        float2 s = *reinterpret_cast<const float2*>(&Sb[j * DD + kp * 2]);
        float t0 = tanh_fast(s.x + sRv[kp * 2]);
        float t1 = tanh_fast(s.y + sRv[kp * 2 + 1]);
        __nv_bfloat16 h0 = __float2bfloat16(t0);
        __nv_bfloat16 h1 = __float2bfloat16(t1);
        sThi[j * STU + kp] = ((uint32_t)__bfloat16_as_ushort(h1) << 16) | __bfloat16_as_ushort(h0);
        sTlo[j * STU + kp] = pack_bf16x2(t0 - __bfloat162float(h0), t1 - __bfloat162float(h1));
    }
    __syncthreads();

    // ---- HMMA main: warp (wm, wn); warp owns 3 m-tiles x 2 n-tiles ----
    const int wn = wid & 3;
    const int wm = wid >> 2;
    const int d0 = wn * 16;

    const uint32_t tThi = smem_u32(sThi);
    const uint32_t tTlo = smem_u32(sTlo);
    const uint32_t tWhi = smem_u32(sWhi);
    const uint32_t tWlo = smem_u32(sWlo);

    const int a_joff = (lane & 7) + ((lane & 8) ? 8 : 0);
    const int a_koff = (lane & 16) ? 8 : 0;
    const int bl     = lane & 15;
    const int b_nrow = bl & 7;
    const int b_koff = (bl & 8) ? 8 : 0;

    float c[3][2][4];
#pragma unroll
    for (int mt = 0; mt < 3; mt++)
#pragma unroll
        for (int nt = 0; nt < 2; nt++)
#pragma unroll
            for (int r = 0; r < 4; r++) c[mt][nt][r] = 0.0f;

#pragma unroll
    for (int pass = 0; pass < 3; pass++) {
        const uint32_t Ab = (pass == 1) ? tTlo : tThi;
        const uint32_t Bb = (pass == 2) ? tWlo : tWhi;
#pragma unroll
        for (int ks = 0; ks < 4; ks++) {
            const int k0 = ks * 16;
            uint32_t bf[2][2];
#pragma unroll
            for (int nt = 0; nt < 2; nt++) {
                uint32_t baddr = Bb + ((d0 + nt * 8 + b_nrow) * STU + ((k0 + b_koff) >> 1)) * 4;
                ldm_x2(bf[nt][0], bf[nt][1], baddr);
            }
#pragma unroll
            for (int mt = 0; mt < 3; mt++) {
                const int jm = (wm * 3 + mt) * 16;
                uint32_t af[4];
                uint32_t aaddr = Ab + ((jm + a_joff) * STU + ((k0 + a_koff) >> 1)) * 4;
                ldm_x4(af, aaddr);
                mma_bf16(c[mt][0], af, bf[0][0], bf[0][1]);
                mma_bf16(c[mt][1], af, bf[1][0], bf[1][1]);
            }
        }
    }

    // ---- epilogue: tanh + adj-weighted j-reduction in fragments ----
    const int g4 = lane >> 2;
    const int c4 = lane & 3;
    float acc[2][2] = {{0.f, 0.f}, {0.f, 0.f}};
    float b2v[2][2];
#pragma unroll
    for (int nt = 0; nt < 2; nt++) {
        b2v[nt][0] = sB2[d0 + nt * 8 + 2 * c4];
        b2v[nt][1] = sB2[d0 + nt * 8 + 2 * c4 + 1];
    }
#pragma unroll
    for (int mt = 0; mt < 3; mt++) {
        const int jb = (wm * 3 + mt) * 16;
        float aj0 = sAdj[jb + g4];
        float aj1 = sAdj[jb + 8 + g4];
#pragma unroll
        for (int nt = 0; nt < 2; nt++) {
            acc[nt][0] = fmaf(aj0, tanh_fast(c[mt][nt][0] + b2v[nt][0]), acc[nt][0]);
            acc[nt][1] = fmaf(aj0, tanh_fast(c[mt][nt][1] + b2v[nt][1]), acc[nt][1]);
            acc[nt][0] = fmaf(aj1, tanh_fast(c[mt][nt][2] + b2v[nt][0]), acc[nt][0]);
            acc[nt][1] = fmaf(aj1, tanh_fast(c[mt][nt][3] + b2v[nt][1]), acc[nt][1]);
        }
    }
#pragma unroll
    for (int off = 4; off <= 16; off <<= 1) {
#pragma unroll
        for (int nt = 0; nt < 2; nt++) {
#pragma unroll
            for (int cc = 0; cc < 2; cc++)
                acc[nt][cc] += __shfl_xor_sync(0xffffffffu, acc[nt][cc], off);
        }
    }
    if (lane < 4) {
        sRed[wm][d0 + 2 * lane]         = acc[0][0];
        sRed[wm][d0 + 2 * lane + 1]     = acc[0][1];
        sRed[wm][d0 + 8 + 2 * lane]     = acc[1][0];
        sRed[wm][d0 + 8 + 2 * lane + 1] = acc[1][1];
    }
    __syncthreads();

    // ---- phase 2: alias scratch onto dead sThi region ----
    float* sAgg  = reinterpret_cast<float*>(sThi);        // [64]
    float* sGate = sAgg + DD;                             // [3*64]
    float* sHN   = sGate + 3 * DD;                        // [64]
    float* sP    = sHN + DD;                              // [64]
    float* sP2   = sP + DD;                               // [64]

    if (tid < DD)
        sAgg[tid] = (sRed[0][tid] + sRed[1][tid]) * (1.0f / 96.0f);
    __syncthreads();

    // Stage A: GRU gate pre-activations  (warps 0..5: 3 GEMVs x 2 warps)
    if (wid < 6) {
        const int g = wid >> 1;
        const int d = (wid & 1) * 32 + lane;
        const float* W = (g == 0) ? W_hr : (g == 1) ? W_hi : W_hh;
        float a = 0.0f;
#pragma unroll 8
        for (int k = 0; k < DD; k++) a = fmaf(sAgg[k], W[k * DD + d], a);
        sGate[g * DD + d] = a;
    }
    __syncthreads();

    // GRU update (64 threads)
    if (tid < DD) {
        const int d = tid;
        int skill = skill_seq[b * TT + t];
        const float* X = &g_Xall[skill * (3 * DD)];
        float rr = sigmoid_acc(X[d] + sGate[d]);
        float ii = sigmoid_acc(X[DD + d] + sGate[DD + d]);
        float nn = tanhf(X[2 * DD + d] + rr * sGate[2 * DD + d]);
        float h  = g_hidden[row + d];
        float hn = (1.0f - ii) * nn + ii * h;
        g_hidden[row + d] = hn;
        sHN[d] = hn;
    }
    __syncthreads();

    // Stage B: pred layer1 + Snext + R  (warps 0..5)
    if (wid < 6) {
        const int g = wid >> 1;
        const int d = (wid & 1) * 32 + lane;
        const float* W = (g == 0) ? W_o1 : (g == 1) ? W_msg1 : (W_msg1 + DD * DD);
        float a = 0.0f;
#pragma unroll 8
        for (int k = 0; k < DD; k++) a = fmaf(sHN[k], W[k * DD + d], a);
        if (g == 0)      sP[d] = fmaxf(a + b_o1[d], 0.0f);
        else if (g == 1) Snext[row + d] = a;
        else             g_R[row + d] = a;
    }
    __syncthreads();

    // Stage C: pred layer2 (warps 0..1)
    if (wid < 2) {
        const int d = wid * 32 + lane;
        float a = 0.0f;
#pragma unroll 8
        for (int k = 0; k < DD; k++) a = fmaf(sP[k], W_o2[k * DD + d], a);
        sP2[d] = fmaxf(a + b_o2[d], 0.0f);
    }
    __syncthreads();

    // Stage D: pred layer3 -> out (warps 0..1)
    if (wid < 2) {
        const int d = wid * 32 + lane;
        float a = 0.0f;
#pragma unroll 8
        for (int k = 0; k < DD; k++) a = fmaf(sP2[k], W_o3[k * DD + d], a);
        out[(((size_t)b * 12 + t) * NB + i) * DD + d] = a + b_o3[d];
    }
}

// ---------------------------------------------------------------------------
extern "C" void kernel_launch(void* const* d_in, const int* in_sizes, int n_in,
                              void* d_out, int out_size) {
    const int*   skill_seq = (const int*)  d_in[0];
    const float* adj       = (const float*)d_in[1];
    const float* node_emb  = (const float*)d_in[2];
    const float* W_msg1    = (const float*)d_in[3];
    const float* b_msg1    = (const float*)d_in[4];
    const float* W_msg2    = (const float*)d_in[5];
    const float* b_msg2    = (const float*)d_in[6];
    const float* W_hr      = (const float*)d_in[7];
    const float* W_hi      = (const float*)d_in[8];
    const float* W_hh      = (const float*)d_in[9];
    const float* W_ir      = (const float*)d_in[10];
    const float* b_ir      = (const float*)d_in[11];
    const float* W_ii      = (const float*)d_in[12];
    const float* b_ii      = (const float*)d_in[13];
    const float* W_in      = (const float*)d_in[14];
    const float* b_in      = (const float*)d_in[15];
    const float* W_o1      = (const float*)d_in[16];
    const float* b_o1      = (const float*)d_in[17];
    const float* W_o2      = (const float*)d_in[18];
    const float* b_o2      = (const float*)d_in[19];
    const float* W_o3      = (const float*)d_in[20];
    const float* b_o3      = (const float*)d_in[21];
    float* out = (float*)d_out;

    kInit<<<(SZ + 255) / 256, 256>>>();
    kPrep<<<1, 256>>>(W_msg2);
    kPrepX<<<NB, 192>>>(node_emb, W_ir, b_ir, W_ii, b_ii, W_in, b_in);

    for (int t = 0; t < TT - 1; t++) {
        kStep<<<BS * NB, 256>>>(t, skill_seq, adj,
                                b_msg1, b_msg2,
                                W_hr, W_hi, W_hh,
                                W_o1, b_o1, W_o2, b_o2, W_o3, b_o3,
                                W_msg1, out);
    }
}

// round 7
// speedup vs baseline: 1.9230x; 1.9071x over previous
#include <cuda_runtime.h>
#include <cuda_bf16.h>
#include <math.h>
#include <stdint.h>

// Problem constants
#define NB   96   // nodes
#define DD   64   // feature dim
#define BS   16   // batch
#define TT   13   // sequence length (12 steps)
#define SZ   (BS * NB * DD)

#define STU  36   // shared row stride in u32 (= 72 bf16): conflict-free ldmatrix

// Scratch state (allocation-free rule: __device__ globals)
__device__ float g_hidden[SZ];
__device__ float g_S[SZ];
__device__ float g_R[SZ];
__device__ float g_agg[SZ];
__device__ float g_Xall[NB * 3 * DD];   // per-skill input projections (xr|xi|xn), bias included

// W2^T split into bf16 hi/lo, packed 2 k's per u32: layout [d][kp]
__device__ uint32_t g_w2t_hi[2048];
__device__ uint32_t g_w2t_lo[2048];

__device__ __forceinline__ float tanh_fast(float x) {
    float y;
    asm("tanh.approx.f32 %0, %1;" : "=f"(y) : "f"(x));
    return y;
}
__device__ __forceinline__ float sigmoid_acc(float x) {
    return 1.0f / (1.0f + expf(-x));
}
__device__ __forceinline__ uint32_t smem_u32(const void* p) {
    uint32_t a;
    asm("{ .reg .u64 t; cvta.to.shared.u64 t, %1; cvt.u32.u64 %0, t; }" : "=r"(a) : "l"(p));
    return a;
}
__device__ __forceinline__ void ldm_x4(uint32_t a[4], uint32_t addr) {
    asm volatile("ldmatrix.sync.aligned.m8n8.x4.shared.b16 {%0,%1,%2,%3}, [%4];"
        : "=r"(a[0]), "=r"(a[1]), "=r"(a[2]), "=r"(a[3]) : "r"(addr));
}
__device__ __forceinline__ void ldm_x2(uint32_t& r0, uint32_t& r1, uint32_t addr) {
    asm volatile("ldmatrix.sync.aligned.m8n8.x2.shared.b16 {%0,%1}, [%2];"
        : "=r"(r0), "=r"(r1) : "r"(addr));
}
__device__ __forceinline__ void mma_bf16(float c[4], const uint32_t a[4],
                                         uint32_t b0, uint32_t b1) {
    asm volatile("mma.sync.aligned.m16n8k16.row.col.f32.bf16.bf16.f32 "
        "{%0,%1,%2,%3}, {%4,%5,%6,%7}, {%8,%9}, {%0,%1,%2,%3};"
        : "+f"(c[0]), "+f"(c[1]), "+f"(c[2]), "+f"(c[3])
        : "r"(a[0]), "r"(a[1]), "r"(a[2]), "r"(a[3]), "r"(b0), "r"(b1));
}
__device__ __forceinline__ uint32_t pack_bf16x2(float lo_val, float hi_val) {
    __nv_bfloat16 l = __float2bfloat16(lo_val);
    __nv_bfloat16 h = __float2bfloat16(hi_val);
    return ((uint32_t)__bfloat16_as_ushort(h) << 16) | __bfloat16_as_ushort(l);
}

// ---------------------------------------------------------------------------
__global__ void kInit() {
    int idx = blockIdx.x * blockDim.x + threadIdx.x;
    if (idx < SZ) {
        g_hidden[idx] = 0.0f;
        g_S[idx] = 0.0f;
        g_R[idx] = 0.0f;
    }
}

// Prep (once): Wt[d][k] = W2[k][d], bf16 hi/lo split, 2 k's packed per u32.
__global__ void kPrep(const float* __restrict__ W2) {
    int tid = threadIdx.x;
    for (int idx = tid; idx < 2048; idx += 256) {
        int d  = idx >> 5;
        int kp = idx & 31;
        float w0 = W2[(2 * kp)     * DD + d];
        float w1 = W2[(2 * kp + 1) * DD + d];
        __nv_bfloat16 h0 = __float2bfloat16(w0);
        __nv_bfloat16 h1 = __float2bfloat16(w1);
        g_w2t_hi[idx] = ((uint32_t)__bfloat16_as_ushort(h1) << 16) | __bfloat16_as_ushort(h0);
        g_w2t_lo[idx] = pack_bf16x2(w0 - __bfloat162float(h0), w1 - __bfloat162float(h1));
    }
}

// Prep (once): per-skill input projections Xall[s][g*64+d] = b_g[d] + emb[s]@W_g
__global__ void kPrepX(const float* __restrict__ emb,
                       const float* __restrict__ W_ir, const float* __restrict__ b_ir,
                       const float* __restrict__ W_ii, const float* __restrict__ b_ii,
                       const float* __restrict__ W_in, const float* __restrict__ b_in) {
    __shared__ float sE[DD];
    int s = blockIdx.x;
    int tid = threadIdx.x;          // 192 threads
    if (tid < DD) sE[tid] = emb[s * DD + tid];
    __syncthreads();
    int g = tid >> 6, d = tid & 63;
    const float* W  = (g == 0) ? W_ir : (g == 1) ? W_ii : W_in;
    const float* bb = (g == 0) ? b_ir : (g == 1) ? b_ii : b_in;
    float a = bb[d];
#pragma unroll 8
    for (int k = 0; k < DD; k++) a = fmaf(sE[k], W[k * DD + d], a);
    g_Xall[s * (3 * DD) + g * DD + d] = a;
}

// ---------------------------------------------------------------------------
// Kernel B (heavy, HMMA): per (b,i) CTA:
//   T[j,k]   = tanh(S[b,j,k] + R[b,i,k] + bm1[k])       (96x64, bf16 hi/lo)
//   C[j,d]   = T@W2  (3-term bf16 split: Thi*Whi + Tlo*Whi + Thi*Wlo)
//   agg[b,i,d] = (1/96)*sum_j adj[b,i,j]*tanh(C[j,d]+b2[d])
// ks-major loop: each fragment ldmatrix'd exactly once.
// ---------------------------------------------------------------------------
__global__ void __launch_bounds__(256, 4) kB(
    const float* __restrict__ adj,     // (1,16,96,96)
    const float* __restrict__ bm1,     // (64)
    const float* __restrict__ b2)      // (64)
{
    __shared__ uint32_t sThi[NB * STU];   // 13824 B
    __shared__ uint32_t sTlo[NB * STU];   // 13824 B
    __shared__ uint32_t sWhi[DD * STU];   //  9216 B
    __shared__ uint32_t sWlo[DD * STU];   //  9216 B
    __shared__ float sAdj[NB];
    __shared__ float sB2[DD];
    __shared__ float sRv[DD];
    __shared__ float sRed[2][DD];

    const int bx   = blockIdx.x;
    const int b    = bx / NB;
    const int i    = bx % NB;
    const int tid  = threadIdx.x;
    const int wid  = tid >> 5;
    const int lane = tid & 31;

    // stage W images + adj row + biases
    for (int idx = tid; idx < 2048; idx += 256) {
        int d = idx >> 5, kp = idx & 31;
        sWhi[d * STU + kp] = g_w2t_hi[idx];
        sWlo[d * STU + kp] = g_w2t_lo[idx];
    }
    if (tid < DD) {
        sRv[tid] = g_R[(b * NB + i) * DD + tid] + bm1[tid];
        sB2[tid] = b2[tid];
    }
    if (tid < NB) sAdj[tid] = adj[(b * NB + i) * NB + tid];
    __syncthreads();

    // build T = tanh(S[b,j,:] + rv) -> bf16 hi/lo (2 k's per u32)
    const float* Sb = &g_S[b * NB * DD];
#pragma unroll
    for (int p = 0; p < 12; p++) {
        int idx = tid + p * 256;          // 0..3071
        int j  = idx >> 5;
        int kp = idx & 31;
        float2 s = *reinterpret_cast<const float2*>(&Sb[j * DD + kp * 2]);
        float t0 = tanh_fast(s.x + sRv[kp * 2]);
        float t1 = tanh_fast(s.y + sRv[kp * 2 + 1]);
        __nv_bfloat16 h0 = __float2bfloat16(t0);
        __nv_bfloat16 h1 = __float2bfloat16(t1);
        sThi[j * STU + kp] = ((uint32_t)__bfloat16_as_ushort(h1) << 16) | __bfloat16_as_ushort(h0);
        sTlo[j * STU + kp] = pack_bf16x2(t0 - __bfloat162float(h0), t1 - __bfloat162float(h1));
    }
    __syncthreads();

    // ---- HMMA main: warp (wm, wn); warp owns 3 m-tiles x 2 n-tiles ----
    const int wn = wid & 3;
    const int wm = wid >> 2;
    const int d0 = wn * 16;

    const uint32_t tThi = smem_u32(sThi);
    const uint32_t tTlo = smem_u32(sTlo);
    const uint32_t tWhi = smem_u32(sWhi);
    const uint32_t tWlo = smem_u32(sWlo);

    const int a_joff = (lane & 7) + ((lane & 8) ? 8 : 0);
    const int a_koff = (lane & 16) ? 8 : 0;
    const int bl     = lane & 15;
    const int b_nrow = bl & 7;
    const int b_koff = (bl & 8) ? 8 : 0;

    float c[3][2][4];
#pragma unroll
    for (int mt = 0; mt < 3; mt++)
#pragma unroll
        for (int nt = 0; nt < 2; nt++)
#pragma unroll
            for (int r = 0; r < 4; r++) c[mt][nt][r] = 0.0f;

    // ks-major: every fragment loaded exactly once; 3-term split from registers
#pragma unroll
    for (int ks = 0; ks < 4; ks++) {
        const int k0 = ks * 16;
        uint32_t bhi[2][2], blo[2][2];
#pragma unroll
        for (int nt = 0; nt < 2; nt++) {
            uint32_t boff = ((d0 + nt * 8 + b_nrow) * STU + ((k0 + b_koff) >> 1)) * 4;
            ldm_x2(bhi[nt][0], bhi[nt][1], tWhi + boff);
            ldm_x2(blo[nt][0], blo[nt][1], tWlo + boff);
        }
#pragma unroll
        for (int mt = 0; mt < 3; mt++) {
            const int jm = (wm * 3 + mt) * 16;
            uint32_t aoff = ((jm + a_joff) * STU + ((k0 + a_koff) >> 1)) * 4;
            uint32_t ahi[4], alo[4];
            ldm_x4(ahi, tThi + aoff);
            ldm_x4(alo, tTlo + aoff);
#pragma unroll
            for (int nt = 0; nt < 2; nt++) {
                mma_bf16(c[mt][nt], ahi, bhi[nt][0], bhi[nt][1]);
                mma_bf16(c[mt][nt], alo, bhi[nt][0], bhi[nt][1]);
                mma_bf16(c[mt][nt], ahi, blo[nt][0], blo[nt][1]);
            }
        }
    }

    // ---- epilogue: tanh + adj-weighted j-reduction in fragments ----
    const int g4 = lane >> 2;
    const int c4 = lane & 3;
    float acc[2][2] = {{0.f, 0.f}, {0.f, 0.f}};
    float b2v[2][2];
#pragma unroll
    for (int nt = 0; nt < 2; nt++) {
        b2v[nt][0] = sB2[d0 + nt * 8 + 2 * c4];
        b2v[nt][1] = sB2[d0 + nt * 8 + 2 * c4 + 1];
    }
#pragma unroll
    for (int mt = 0; mt < 3; mt++) {
        const int jb = (wm * 3 + mt) * 16;
        float aj0 = sAdj[jb + g4];
        float aj1 = sAdj[jb + 8 + g4];
#pragma unroll
        for (int nt = 0; nt < 2; nt++) {
            acc[nt][0] = fmaf(aj0, tanh_fast(c[mt][nt][0] + b2v[nt][0]), acc[nt][0]);
            acc[nt][1] = fmaf(aj0, tanh_fast(c[mt][nt][1] + b2v[nt][1]), acc[nt][1]);
            acc[nt][0] = fmaf(aj1, tanh_fast(c[mt][nt][2] + b2v[nt][0]), acc[nt][0]);
            acc[nt][1] = fmaf(aj1, tanh_fast(c[mt][nt][3] + b2v[nt][1]), acc[nt][1]);
        }
    }
#pragma unroll
    for (int off = 4; off <= 16; off <<= 1) {
#pragma unroll
        for (int nt = 0; nt < 2; nt++) {
#pragma unroll
            for (int cc = 0; cc < 2; cc++)
                acc[nt][cc] += __shfl_xor_sync(0xffffffffu, acc[nt][cc], off);
        }
    }
    if (lane < 4) {
        sRed[wm][d0 + 2 * lane]         = acc[0][0];
        sRed[wm][d0 + 2 * lane + 1]     = acc[0][1];
        sRed[wm][d0 + 8 + 2 * lane]     = acc[1][0];
        sRed[wm][d0 + 8 + 2 * lane + 1] = acc[1][1];
    }
    __syncthreads();
    if (tid < DD)
        g_agg[(b * NB + i) * DD + tid] = (sRed[0][tid] + sRed[1][tid]) * (1.0f / 96.0f);
}

// ---------------------------------------------------------------------------
// Kernel C (light): GRU update + pred head + next-step S/R.
// grid = 384 blocks: b = bx/24, rows n0 = (bx%24)*4; 256 thr = 4 rowgrp x 64 d,
// one row per rowgroup. Input projections precomputed in g_Xall.
// ---------------------------------------------------------------------------
#define RPB 4    // rows per block

__global__ void __launch_bounds__(256) kC(
    int t,
    const int*   __restrict__ skill_seq,  // (16,13)
    const float* __restrict__ W_hr, const float* __restrict__ W_hi,
    const float* __restrict__ W_hh,
    const float* __restrict__ W_o1, const float* __restrict__ b_o1,
    const float* __restrict__ W_o2, const float* __restrict__ b_o2,
    const float* __restrict__ W_o3, const float* __restrict__ b_o3,
    const float* __restrict__ W_msg1,     // (128,64)
    float* __restrict__ out)              // (1,16,12,96,64)
{
    __shared__ float sA[RPB * DD];
    __shared__ float sHN[RPB * DD];
    __shared__ float sP[RPB * DD];
    __shared__ float sP2[RPB * DD];

    const int bx  = blockIdx.x;
    const int b   = bx / 24;
    const int n0  = (bx % 24) * RPB;
    const int tid = threadIdx.x;
    const int d   = tid & 63;
    const int rg  = tid >> 6;             // 0..3, one row each

    const int base = (b * NB + n0) * DD;
    for (int idx = tid; idx < RPB * DD; idx += 256)
        sA[idx] = g_agg[base + idx];
    __syncthreads();

    const int rowoff = rg * DD;

    // Stage A: GRU gates + hidden update
    {
        float ahr = 0.f, ahi = 0.f, ahh = 0.f;
#pragma unroll 8
        for (int k = 0; k < DD; k++) {
            float av = sA[rowoff + k];
            ahr = fmaf(av, W_hr[k * DD + d], ahr);
            ahi = fmaf(av, W_hi[k * DD + d], ahi);
            ahh = fmaf(av, W_hh[k * DD + d], ahh);
        }
        int skill = skill_seq[b * TT + t];
        const float* X = &g_Xall[skill * (3 * DD)];
        float rr = sigmoid_acc(X[d] + ahr);
        float ii = sigmoid_acc(X[DD + d] + ahi);
        float nn = tanhf(X[2 * DD + d] + rr * ahh);
        float h  = g_hidden[base + rowoff + d];
        float hn = (1.0f - ii) * nn + ii * h;
        g_hidden[base + rowoff + d] = hn;
        sHN[rowoff + d] = hn;
    }
    __syncthreads();

    // Stage B: pred layer1 + Snext + R
    {
        float ap = 0.f, aS = 0.f, aR = 0.f;
#pragma unroll 8
        for (int k = 0; k < DD; k++) {
            float hv = sHN[rowoff + k];
            ap = fmaf(hv, W_o1[k * DD + d], ap);
            aS = fmaf(hv, W_msg1[k * DD + d], aS);
            aR = fmaf(hv, W_msg1[(DD + k) * DD + d], aR);
        }
        sP[rowoff + d] = fmaxf(ap + b_o1[d], 0.0f);
        g_S[base + rowoff + d] = aS;
        g_R[base + rowoff + d] = aR;
    }
    __syncthreads();

    // Stage C: pred layer2
    {
        float a = 0.f;
#pragma unroll 8
        for (int k = 0; k < DD; k++) a = fmaf(sP[rowoff + k], W_o2[k * DD + d], a);
        sP2[rowoff + d] = fmaxf(a + b_o2[d], 0.0f);
    }
    __syncthreads();

    // Stage D: pred layer3 -> out
    {
        float a = 0.f;
#pragma unroll 8
        for (int k = 0; k < DD; k++) a = fmaf(sP2[rowoff + k], W_o3[k * DD + d], a);
        out[(((size_t)b * 12 + t) * NB + (n0 + rg)) * DD + d] = a + b_o3[d];
    }
}

// ---------------------------------------------------------------------------
extern "C" void kernel_launch(void* const* d_in, const int* in_sizes, int n_in,
                              void* d_out, int out_size) {
    const int*   skill_seq = (const int*)  d_in[0];
    const float* adj       = (const float*)d_in[1];
    const float* node_emb  = (const float*)d_in[2];
    const float* W_msg1    = (const float*)d_in[3];
    const float* b_msg1    = (const float*)d_in[4];
    const float* W_msg2    = (const float*)d_in[5];
    const float* b_msg2    = (const float*)d_in[6];
    const float* W_hr      = (const float*)d_in[7];
    const float* W_hi      = (const float*)d_in[8];
    const float* W_hh      = (const float*)d_in[9];
    const float* W_ir      = (const float*)d_in[10];
    const float* b_ir      = (const float*)d_in[11];
    const float* W_ii      = (const float*)d_in[12];
    const float* b_ii      = (const float*)d_in[13];
    const float* W_in      = (const float*)d_in[14];
    const float* b_in      = (const float*)d_in[15];
    const float* W_o1      = (const float*)d_in[16];
    const float* b_o1      = (const float*)d_in[17];
    const float* W_o2      = (const float*)d_in[18];
    const float* b_o2      = (const float*)d_in[19];
    const float* W_o3      = (const float*)d_in[20];
    const float* b_o3      = (const float*)d_in[21];
    float* out = (float*)d_out;

    kInit<<<(SZ + 255) / 256, 256>>>();
    kPrep<<<1, 256>>>(W_msg2);
    kPrepX<<<NB, 192>>>(node_emb, W_ir, b_ir, W_ii, b_ii, W_in, b_in);

    for (int t = 0; t < TT - 1; t++) {
        kB<<<BS * NB, 256>>>(adj, b_msg1, b_msg2);
        kC<<<BS * 24, 256>>>(t, skill_seq,
                             W_hr, W_hi, W_hh,
                             W_o1, b_o1, W_o2, b_o2, W_o3, b_o3,
                             W_msg1, out);
    }
}

// round 8
// speedup vs baseline: 2.7061x; 1.4072x over previous
#include <cuda_runtime.h>
#include <cuda_bf16.h>
#include <math.h>
#include <stdint.h>

// Problem constants
#define NB   96   // nodes
#define DD   64   // feature dim
#define BS   16   // batch
#define TT   13   // sequence length (12 steps)
#define SZ   (BS * NB * DD)

#define STU  36   // shared row stride in u32 (= 72 bf16): conflict-free ldmatrix

// Scratch state (allocation-free rule: __device__ globals)
__device__ float g_hidden[SZ];
__device__ float g_S[SZ];
__device__ float g_R[SZ];
__device__ float g_agg[SZ];
__device__ float g_Xall[NB * 3 * DD];   // per-skill input projections (xr|xi|xn)

// W2^T split into bf16 hi/lo, packed 2 k's per u32: layout [d][kp]
__device__ uint32_t g_w2t_hi[2048];
__device__ uint32_t g_w2t_lo[2048];

__device__ __forceinline__ float tanh_fast(float x) {
    float y;
    asm("tanh.approx.f32 %0, %1;" : "=f"(y) : "f"(x));
    return y;
}
__device__ __forceinline__ float sigmoid_acc(float x) {
    return 1.0f / (1.0f + expf(-x));
}
__device__ __forceinline__ uint32_t smem_u32(const void* p) {
    uint32_t a;
    asm("{ .reg .u64 t; cvta.to.shared.u64 t, %1; cvt.u32.u64 %0, t; }" : "=r"(a) : "l"(p));
    return a;
}
__device__ __forceinline__ void ldm_x4(uint32_t a[4], uint32_t addr) {
    asm volatile("ldmatrix.sync.aligned.m8n8.x4.shared.b16 {%0,%1,%2,%3}, [%4];"
        : "=r"(a[0]), "=r"(a[1]), "=r"(a[2]), "=r"(a[3]) : "r"(addr));
}
__device__ __forceinline__ void ldm_x2(uint32_t& r0, uint32_t& r1, uint32_t addr) {
    asm volatile("ldmatrix.sync.aligned.m8n8.x2.shared.b16 {%0,%1}, [%2];"
        : "=r"(r0), "=r"(r1) : "r"(addr));
}
__device__ __forceinline__ void mma_bf16(float c[4], const uint32_t a[4],
                                         uint32_t b0, uint32_t b1) {
    asm volatile("mma.sync.aligned.m16n8k16.row.col.f32.bf16.bf16.f32 "
        "{%0,%1,%2,%3}, {%4,%5,%6,%7}, {%8,%9}, {%0,%1,%2,%3};"
        : "+f"(c[0]), "+f"(c[1]), "+f"(c[2]), "+f"(c[3])
        : "r"(a[0]), "r"(a[1]), "r"(a[2]), "r"(a[3]), "r"(b0), "r"(b1));
}
__device__ __forceinline__ uint32_t pack_bf16x2(float lo_val, float hi_val) {
    __nv_bfloat16 l = __float2bfloat16(lo_val);
    __nv_bfloat16 h = __float2bfloat16(hi_val);
    return ((uint32_t)__bfloat16_as_ushort(h) << 16) | __bfloat16_as_ushort(l);
}

// ---------------------------------------------------------------------------
__global__ void kInit() {
    int idx = blockIdx.x * blockDim.x + threadIdx.x;
    if (idx < SZ) {
        g_hidden[idx] = 0.0f;
        g_S[idx] = 0.0f;
        g_R[idx] = 0.0f;
    }
}

// Prep (once): Wt[d][k] = W2[k][d], bf16 hi/lo split, 2 k's packed per u32.
__global__ void kPrep(const float* __restrict__ W2) {
    int tid = threadIdx.x;
    for (int idx = tid; idx < 2048; idx += 256) {
        int d  = idx >> 5;
        int kp = idx & 31;
        float w0 = W2[(2 * kp)     * DD + d];
        float w1 = W2[(2 * kp + 1) * DD + d];
        __nv_bfloat16 h0 = __float2bfloat16(w0);
        __nv_bfloat16 h1 = __float2bfloat16(w1);
        g_w2t_hi[idx] = ((uint32_t)__bfloat16_as_ushort(h1) << 16) | __bfloat16_as_ushort(h0);
        g_w2t_lo[idx] = pack_bf16x2(w0 - __bfloat162float(h0), w1 - __bfloat162float(h1));
    }
}

// Prep (once): per-skill input projections Xall[s][g*64+d] = b_g[d] + emb[s]@W_g
__global__ void kPrepX(const float* __restrict__ emb,
                       const float* __restrict__ W_ir, const float* __restrict__ b_ir,
                       const float* __restrict__ W_ii, const float* __restrict__ b_ii,
                       const float* __restrict__ W_in, const float* __restrict__ b_in) {
    __shared__ float sE[DD];
    int s = blockIdx.x;
    int tid = threadIdx.x;          // 192 threads
    if (tid < DD) sE[tid] = emb[s * DD + tid];
    __syncthreads();
    int g = tid >> 6, d = tid & 63;
    const float* W  = (g == 0) ? W_ir : (g == 1) ? W_ii : W_in;
    const float* bb = (g == 0) ? b_ir : (g == 1) ? b_ii : b_in;
    float a = bb[d];
#pragma unroll 8
    for (int k = 0; k < DD; k++) a = fmaf(sE[k], W[k * DD + d], a);
    g_Xall[s * (3 * DD) + g * DD + d] = a;
}

// ---------------------------------------------------------------------------
// Kernel B (heavy, HMMA): W fragments hoisted to registers; hot loop = A-ldm only.
// ---------------------------------------------------------------------------
__global__ void __launch_bounds__(256, 3) kB(
    const float* __restrict__ adj,     // (1,16,96,96)
    const float* __restrict__ bm1,     // (64)
    const float* __restrict__ b2)      // (64)
{
    __shared__ uint32_t sThi[NB * STU];   // 13824 B
    __shared__ uint32_t sTlo[NB * STU];   // 13824 B
    __shared__ uint32_t sWhi[DD * STU];   //  9216 B
    __shared__ uint32_t sWlo[DD * STU];   //  9216 B
    __shared__ float sAdj[NB];
    __shared__ float sB2[DD];
    __shared__ float sRv[DD];
    __shared__ float sRed[2][DD];

    const int bx   = blockIdx.x;
    const int b    = bx / NB;
    const int i    = bx % NB;
    const int tid  = threadIdx.x;
    const int wid  = tid >> 5;
    const int lane = tid & 31;

    // stage W images + adj row + biases
    for (int idx = tid; idx < 2048; idx += 256) {
        int d = idx >> 5, kp = idx & 31;
        sWhi[d * STU + kp] = g_w2t_hi[idx];
        sWlo[d * STU + kp] = g_w2t_lo[idx];
    }
    if (tid < DD) {
        sRv[tid] = g_R[(b * NB + i) * DD + tid] + bm1[tid];
        sB2[tid] = b2[tid];
    }
    if (tid < NB) sAdj[tid] = adj[(b * NB + i) * NB + tid];
    __syncthreads();

    // ---- hoist W fragments into registers (once) ----
    const int wn = wid & 3;
    const int wm = wid >> 2;
    const int d0 = wn * 16;

    const uint32_t tThi = smem_u32(sThi);
    const uint32_t tTlo = smem_u32(sTlo);
    const uint32_t tWhi = smem_u32(sWhi);
    const uint32_t tWlo = smem_u32(sWlo);

    const int a_joff = (lane & 7) + ((lane & 8) ? 8 : 0);
    const int a_koff = (lane & 16) ? 8 : 0;
    const int bl     = lane & 15;
    const int b_nrow = bl & 7;
    const int b_koff = (bl & 8) ? 8 : 0;

    uint32_t whiF[4][2][2], wloF[4][2][2];
#pragma unroll
    for (int ks = 0; ks < 4; ks++) {
#pragma unroll
        for (int nt = 0; nt < 2; nt++) {
            uint32_t boff = ((d0 + nt * 8 + b_nrow) * STU + ((ks * 16 + b_koff) >> 1)) * 4;
            ldm_x2(whiF[ks][nt][0], whiF[ks][nt][1], tWhi + boff);
            ldm_x2(wloF[ks][nt][0], wloF[ks][nt][1], tWlo + boff);
        }
    }

    // build T = tanh(S[b,j,:] + rv) -> bf16 hi/lo (2 k's per u32)
    const float* Sb = &g_S[b * NB * DD];
#pragma unroll
    for (int p = 0; p < 12; p++) {
        int idx = tid + p * 256;          // 0..3071
        int j  = idx >> 5;
        int kp = idx & 31;
        float2 s = *reinterpret_cast<const float2*>(&Sb[j * DD + kp * 2]);
        float t0 = tanh_fast(s.x + sRv[kp * 2]);
        float t1 = tanh_fast(s.y + sRv[kp * 2 + 1]);
        __nv_bfloat16 h0 = __float2bfloat16(t0);
        __nv_bfloat16 h1 = __float2bfloat16(t1);
        sThi[j * STU + kp] = ((uint32_t)__bfloat16_as_ushort(h1) << 16) | __bfloat16_as_ushort(h0);
        sTlo[j * STU + kp] = pack_bf16x2(t0 - __bfloat162float(h0), t1 - __bfloat162float(h1));
    }
    __syncthreads();

    // ---- HMMA main loop: only A ldmatrix; W from registers ----
    float c[3][2][4];
#pragma unroll
    for (int mt = 0; mt < 3; mt++)
#pragma unroll
        for (int nt = 0; nt < 2; nt++)
#pragma unroll
            for (int r = 0; r < 4; r++) c[mt][nt][r] = 0.0f;

#pragma unroll
    for (int ks = 0; ks < 4; ks++) {
        const int k0 = ks * 16;
#pragma unroll
        for (int mt = 0; mt < 3; mt++) {
            const int jm = (wm * 3 + mt) * 16;
            uint32_t aoff = ((jm + a_joff) * STU + ((k0 + a_koff) >> 1)) * 4;
            uint32_t ahi[4], alo[4];
            ldm_x4(ahi, tThi + aoff);
            ldm_x4(alo, tTlo + aoff);
#pragma unroll
            for (int nt = 0; nt < 2; nt++) {
                mma_bf16(c[mt][nt], ahi, whiF[ks][nt][0], whiF[ks][nt][1]);
                mma_bf16(c[mt][nt], alo, whiF[ks][nt][0], whiF[ks][nt][1]);
                mma_bf16(c[mt][nt], ahi, wloF[ks][nt][0], wloF[ks][nt][1]);
            }
        }
    }

    // ---- epilogue: tanh + adj-weighted j-reduction in fragments ----
    const int g4 = lane >> 2;
    const int c4 = lane & 3;
    float acc[2][2] = {{0.f, 0.f}, {0.f, 0.f}};
    float b2v[2][2];
#pragma unroll
    for (int nt = 0; nt < 2; nt++) {
        b2v[nt][0] = sB2[d0 + nt * 8 + 2 * c4];
        b2v[nt][1] = sB2[d0 + nt * 8 + 2 * c4 + 1];
    }
#pragma unroll
    for (int mt = 0; mt < 3; mt++) {
        const int jb = (wm * 3 + mt) * 16;
        float aj0 = sAdj[jb + g4];
        float aj1 = sAdj[jb + 8 + g4];
#pragma unroll
        for (int nt = 0; nt < 2; nt++) {
            acc[nt][0] = fmaf(aj0, tanh_fast(c[mt][nt][0] + b2v[nt][0]), acc[nt][0]);
            acc[nt][1] = fmaf(aj0, tanh_fast(c[mt][nt][1] + b2v[nt][1]), acc[nt][1]);
            acc[nt][0] = fmaf(aj1, tanh_fast(c[mt][nt][2] + b2v[nt][0]), acc[nt][0]);
            acc[nt][1] = fmaf(aj1, tanh_fast(c[mt][nt][3] + b2v[nt][1]), acc[nt][1]);
        }
    }
#pragma unroll
    for (int off = 4; off <= 16; off <<= 1) {
#pragma unroll
        for (int nt = 0; nt < 2; nt++) {
#pragma unroll
            for (int cc = 0; cc < 2; cc++)
                acc[nt][cc] += __shfl_xor_sync(0xffffffffu, acc[nt][cc], off);
        }
    }
    if (lane < 4) {
        sRed[wm][d0 + 2 * lane]         = acc[0][0];
        sRed[wm][d0 + 2 * lane + 1]     = acc[0][1];
        sRed[wm][d0 + 8 + 2 * lane]     = acc[1][0];
        sRed[wm][d0 + 8 + 2 * lane + 1] = acc[1][1];
    }
    __syncthreads();
    if (tid < DD)
        g_agg[(b * NB + i) * DD + tid] = (sRed[0][tid] + sRed[1][tid]) * (1.0f / 96.0f);
}

// ---------------------------------------------------------------------------
// Kernel C (light, split-K): 384 blocks, 4 rows each; thread = (d, kc).
// Each weight column LDG'd once per CTA; 16-48 independent LDGs in flight/stage.
// ---------------------------------------------------------------------------
#define RPB 4    // rows per block (== number of kc groups)

__global__ void __launch_bounds__(256) kC(
    int t,
    const int*   __restrict__ skill_seq,  // (16,13)
    const float* __restrict__ W_hr, const float* __restrict__ W_hi,
    const float* __restrict__ W_hh,
    const float* __restrict__ W_o1, const float* __restrict__ b_o1,
    const float* __restrict__ W_o2, const float* __restrict__ b_o2,
    const float* __restrict__ W_o3, const float* __restrict__ b_o3,
    const float* __restrict__ W_msg1,     // (128,64)
    float* __restrict__ out)              // (1,16,12,96,64)
{
    __shared__ float sA[RPB * DD];
    __shared__ float sHN[RPB * DD];
    __shared__ float sP[RPB * DD];
    __shared__ float sP2[RPB * DD];
    __shared__ float sPart[4][RPB][3][DD];   // kc, row, gate, d  = 12 KB

    const int bx  = blockIdx.x;
    const int b   = bx / 24;
    const int n0  = (bx % 24) * RPB;
    const int tid = threadIdx.x;
    const int d   = tid & 63;
    const int kc  = tid >> 6;             // 0..3
    const int k0  = kc * 16;

    const int base = (b * NB + n0) * DD;
    for (int idx = tid; idx < RPB * DD; idx += 256)
        sA[idx] = g_agg[base + idx];
    __syncthreads();

    // ---- Stage A: GRU gates (split-K partials) ----
    {
        float pr[RPB], pi[RPB], ph[RPB];
#pragma unroll
        for (int r = 0; r < RPB; r++) { pr[r] = 0.f; pi[r] = 0.f; ph[r] = 0.f; }
#pragma unroll
        for (int kk = 0; kk < 16; kk++) {
            int k = k0 + kk;
            float whr = W_hr[k * DD + d];
            float whi = W_hi[k * DD + d];
            float whh = W_hh[k * DD + d];
#pragma unroll
            for (int r = 0; r < RPB; r++) {
                float av = sA[r * DD + k];
                pr[r] = fmaf(av, whr, pr[r]);
                pi[r] = fmaf(av, whi, pi[r]);
                ph[r] = fmaf(av, whh, ph[r]);
            }
        }
#pragma unroll
        for (int r = 0; r < RPB; r++) {
            sPart[kc][r][0][d] = pr[r];
            sPart[kc][r][1][d] = pi[r];
            sPart[kc][r][2][d] = ph[r];
        }
    }
    __syncthreads();

    // combine + GRU update: thread (d, r=kc)
    {
        const int r = kc;
        float ahr = sPart[0][r][0][d] + sPart[1][r][0][d] + sPart[2][r][0][d] + sPart[3][r][0][d];
        float ahi = sPart[0][r][1][d] + sPart[1][r][1][d] + sPart[2][r][1][d] + sPart[3][r][1][d];
        float ahh = sPart[0][r][2][d] + sPart[1][r][2][d] + sPart[2][r][2][d] + sPart[3][r][2][d];
        int skill = skill_seq[b * TT + t];
        const float* X = &g_Xall[skill * (3 * DD)];
        float rr = sigmoid_acc(X[d] + ahr);
        float ii = sigmoid_acc(X[DD + d] + ahi);
        float nn = tanhf(X[2 * DD + d] + rr * ahh);
        float h  = g_hidden[base + r * DD + d];
        float hn = (1.0f - ii) * nn + ii * h;
        g_hidden[base + r * DD + d] = hn;
        sHN[r * DD + d] = hn;
    }
    __syncthreads();

    // ---- Stage B: pred layer1 + Snext + R (split-K) ----
    {
        float p1[RPB], pS[RPB], pR[RPB];
#pragma unroll
        for (int r = 0; r < RPB; r++) { p1[r] = 0.f; pS[r] = 0.f; pR[r] = 0.f; }
#pragma unroll
        for (int kk = 0; kk < 16; kk++) {
            int k = k0 + kk;
            float w1 = W_o1[k * DD + d];
            float wS = W_msg1[k * DD + d];
            float wR = W_msg1[(DD + k) * DD + d];
#pragma unroll
            for (int r = 0; r < RPB; r++) {
                float hv = sHN[r * DD + k];
                p1[r] = fmaf(hv, w1, p1[r]);
                pS[r] = fmaf(hv, wS, pS[r]);
                pR[r] = fmaf(hv, wR, pR[r]);
            }
        }
#pragma unroll
        for (int r = 0; r < RPB; r++) {
            sPart[kc][r][0][d] = p1[r];
            sPart[kc][r][1][d] = pS[r];
            sPart[kc][r][2][d] = pR[r];
        }
    }
    __syncthreads();
    {
        const int r = kc;
        float a1 = sPart[0][r][0][d] + sPart[1][r][0][d] + sPart[2][r][0][d] + sPart[3][r][0][d];
        float aS = sPart[0][r][1][d] + sPart[1][r][1][d] + sPart[2][r][1][d] + sPart[3][r][1][d];
        float aR = sPart[0][r][2][d] + sPart[1][r][2][d] + sPart[2][r][2][d] + sPart[3][r][2][d];
        sP[r * DD + d] = fmaxf(a1 + b_o1[d], 0.0f);
        g_S[base + r * DD + d] = aS;
        g_R[base + r * DD + d] = aR;
    }
    __syncthreads();

    // ---- Stage C: pred layer2 (split-K) ----
    {
        float p2[RPB];
#pragma unroll
        for (int r = 0; r < RPB; r++) p2[r] = 0.f;
#pragma unroll
        for (int kk = 0; kk < 16; kk++) {
            int k = k0 + kk;
            float w2 = W_o2[k * DD + d];
#pragma unroll
            for (int r = 0; r < RPB; r++)
                p2[r] = fmaf(sP[r * DD + k], w2, p2[r]);
        }
#pragma unroll
        for (int r = 0; r < RPB; r++)
            sPart[kc][r][0][d] = p2[r];
    }
    __syncthreads();
    {
        const int r = kc;
        float a2 = sPart[0][r][0][d] + sPart[1][r][0][d] + sPart[2][r][0][d] + sPart[3][r][0][d];
        sP2[r * DD + d] = fmaxf(a2 + b_o2[d], 0.0f);
    }
    __syncthreads();

    // ---- Stage D: pred layer3 -> out (split-K) ----
    {
        float p3[RPB];
#pragma unroll
        for (int r = 0; r < RPB; r++) p3[r] = 0.f;
#pragma unroll
        for (int kk = 0; kk < 16; kk++) {
            int k = k0 + kk;
            float w3 = W_o3[k * DD + d];
#pragma unroll
            for (int r = 0; r < RPB; r++)
                p3[r] = fmaf(sP2[r * DD + k], w3, p3[r]);
        }
#pragma unroll
        for (int r = 0; r < RPB; r++)
            sPart[kc][r][0][d] = p3[r];
    }
    __syncthreads();
    {
        const int r = kc;
        float a3 = sPart[0][r][0][d] + sPart[1][r][0][d] + sPart[2][r][0][d] + sPart[3][r][0][d];
        out[(((size_t)b * 12 + t) * NB + (n0 + r)) * DD + d] = a3 + b_o3[d];
    }
}

// ---------------------------------------------------------------------------
extern "C" void kernel_launch(void* const* d_in, const int* in_sizes, int n_in,
                              void* d_out, int out_size) {
    const int*   skill_seq = (const int*)  d_in[0];
    const float* adj       = (const float*)d_in[1];
    const float* node_emb  = (const float*)d_in[2];
    const float* W_msg1    = (const float*)d_in[3];
    const float* b_msg1    = (const float*)d_in[4];
    const float* W_msg2    = (const float*)d_in[5];
    const float* b_msg2    = (const float*)d_in[6];
    const float* W_hr      = (const float*)d_in[7];
    const float* W_hi      = (const float*)d_in[8];
    const float* W_hh      = (const float*)d_in[9];
    const float* W_ir      = (const float*)d_in[10];
    const float* b_ir      = (const float*)d_in[11];
    const float* W_ii      = (const float*)d_in[12];
    const float* b_ii      = (const float*)d_in[13];
    const float* W_in      = (const float*)d_in[14];
    const float* b_in      = (const float*)d_in[15];
    const float* W_o1      = (const float*)d_in[16];
    const float* b_o1      = (const float*)d_in[17];
    const float* W_o2      = (const float*)d_in[18];
    const float* b_o2      = (const float*)d_in[19];
    const float* W_o3      = (const float*)d_in[20];
    const float* b_o3      = (const float*)d_in[21];
    float* out = (float*)d_out;

    kInit<<<(SZ + 255) / 256, 256>>>();
    kPrep<<<1, 256>>>(W_msg2);
    kPrepX<<<NB, 192>>>(node_emb, W_ir, b_ir, W_ii, b_ii, W_in, b_in);

    for (int t = 0; t < TT - 1; t++) {
        kB<<<BS * NB, 256>>>(adj, b_msg1, b_msg2);
        kC<<<BS * 24, 256>>>(t, skill_seq,
                             W_hr, W_hi, W_hh,
                             W_o1, b_o1, W_o2, b_o2, W_o3, b_o3,
                             W_msg1, out);
    }
}